// round 13
// baseline (speedup 1.0000x reference)
#include <cuda_runtime.h>
#include <cuda_fp16.h>
#include <cstdint>

#define D_IN  256
#define D_OUT 128

// 16-row fragment counts: movie 6250, dir 3125, act 9375 (+8 pad)
#define FR_MOVIE 6250
#define FR_DIR   3125
#define FR_ACT   9375
#define FR_TOTAL 18758

__device__ uint4 g_xperm[(size_t)FR_TOTAL * 512];  // frag-permuted fp16 X
__device__ uint4 g_wt[7][4096];                    // frag-permuted fp16 W
__device__ float g_bias[384];
// y buffers: dm@0 (50k rows), am@50k (150k), md@200k (100k), ma@300k (100k).
__device__ float g_scratch[(size_t)400000 * 128];
__device__ int g_e_is64;

// CSR-by-dst per relation: slot 0=dm, 1=am, 2=md, 3=ma.
__device__ int g_count[4][150000];
__device__ int g_rowptr[4][150001];
__device__ int g_cursor[4][150000];
__device__ int g_chunks[4][256];
__device__ int g_esrc[4][320000];

struct StreamPack {
    cudaStream_t s2, s3;
    cudaEvent_t ev[10];
    StreamPack() {
        cudaStreamCreateWithFlags(&s2, cudaStreamNonBlocking);
        cudaStreamCreateWithFlags(&s3, cudaStreamNonBlocking);
        for (int i = 0; i < 10; i++) cudaEventCreateWithFlags(&ev[i], cudaEventDisableTiming);
    }
};
static StreamPack g_sp;

__device__ __forceinline__ uint32_t packh2(float x, float y) {
    __half2 h = __floats2half2_rn(x, y);
    return *(uint32_t*)&h;
}
__device__ __forceinline__ uint32_t smem_u32(const void* p) {
    uint32_t a;
    asm("{ .reg .u64 t; cvta.to.shared.u64 t, %1; cvt.u32.u64 %0, t; }" : "=r"(a) : "l"(p));
    return a;
}
__device__ __forceinline__ void mma16(float* d, uint4 a, uint32_t b0, uint32_t b1) {
    asm volatile("mma.sync.aligned.m16n8k16.row.col.f32.f16.f16.f32 "
        "{%0,%1,%2,%3}, {%4,%5,%6,%7}, {%8,%9}, {%0,%1,%2,%3};"
        : "+f"(d[0]), "+f"(d[1]), "+f"(d[2]), "+f"(d[3])
        : "r"(a.x), "r"(a.y), "r"(a.z), "r"(a.w), "r"(b0), "r"(b1));
}

// ---------------------------------------------------------------------------
__global__ void detect_kernel(const int* __restrict__ e32) {
    if (threadIdx.x == 0 && blockIdx.x == 0) {
        int all0 = 1;
        for (int i = 1; i < 64; i += 2) all0 &= (e32[i] == 0);
        g_e_is64 = all0;
    }
}

// ---------------------------------------------------------------------------
// CSR-by-dst build kernels
// ---------------------------------------------------------------------------
__global__ void zero_i32(int* __restrict__ p, int n) {
    int i = blockIdx.x * blockDim.x + threadIdx.x;
    if (i < n) p[i] = 0;
}
__global__ void hist_dst(const int* __restrict__ e32, int E, int* __restrict__ count) {
    int e = blockIdx.x * blockDim.x + threadIdx.x;
    if (e >= E) return;
    int mult = g_e_is64 ? 2 : 1;
    int d = e32[(size_t)(E + e) * mult];
    atomicAdd(&count[d], 1);
}
__global__ void scan_part(const int* __restrict__ cnt, int n, int* __restrict__ sums) {
    __shared__ int sm[256];
    int b = blockIdx.x, t = threadIdx.x;
    int base = b * 2048 + t * 8;
    int s = 0;
    #pragma unroll
    for (int i = 0; i < 8; i++) { int idx = base + i; if (idx < n) s += cnt[idx]; }
    sm[t] = s; __syncthreads();
    for (int o = 128; o > 0; o >>= 1) { if (t < o) sm[t] += sm[t + o]; __syncthreads(); }
    if (t == 0) sums[b] = sm[0];
}
__global__ void scan_chunks(int* __restrict__ sums, int nc) {
    __shared__ int sm[256];
    int t = threadIdx.x;
    int orig = (t < nc) ? sums[t] : 0;
    sm[t] = orig; __syncthreads();
    for (int o = 1; o < 256; o <<= 1) {
        int u = (t >= o) ? sm[t - o] : 0;
        __syncthreads();
        sm[t] += u;
        __syncthreads();
    }
    if (t < nc) sums[t] = sm[t] - orig;   // exclusive
}
__global__ void scan_final(const int* __restrict__ cnt, int n,
                           const int* __restrict__ chunkOff,
                           int* __restrict__ rowptr, int* __restrict__ cursor, int E) {
    __shared__ int sm[256];
    int b = blockIdx.x, t = threadIdx.x;
    int base = b * 2048 + t * 8;
    int v[8]; int s = 0;
    #pragma unroll
    for (int i = 0; i < 8; i++) { int idx = base + i; v[i] = (idx < n) ? cnt[idx] : 0; s += v[i]; }
    int orig = s;
    sm[t] = s; __syncthreads();
    for (int o = 1; o < 256; o <<= 1) {
        int u = (t >= o) ? sm[t - o] : 0;
        __syncthreads();
        sm[t] += u;
        __syncthreads();
    }
    int run = chunkOff[b] + (sm[t] - orig);
    #pragma unroll
    for (int i = 0; i < 8; i++) {
        int idx = base + i;
        if (idx < n) { rowptr[idx] = run; cursor[idx] = run; run += v[i]; }
    }
    if (b == 0 && t == 0) rowptr[n] = E;
}
__global__ void fill_csr(const int* __restrict__ e32, int E,
                         int* __restrict__ cursor, int* __restrict__ esrc) {
    int e = blockIdx.x * blockDim.x + threadIdx.x;
    if (e >= E) return;
    int mult = g_e_is64 ? 2 : 1;
    int s = e32[(size_t)e * mult];
    int d = e32[(size_t)(E + e) * mult];
    int pos = atomicAdd(&cursor[d], 1);
    esrc[pos] = s;
}

// ---------------------------------------------------------------------------
// Prep A (one matrix): permute into m16n8k16 fp16 A-fragment order.
// ---------------------------------------------------------------------------
__global__ void prep_a_one(const float* __restrict__ X, uint4* __restrict__ dst,
                           int nfrags, long long rows)
{
    long long t = (long long)blockIdx.x * blockDim.x + threadIdx.x;
    if (t >= (long long)nfrags * 512) return;
    int l  = (int)(t & 31);
    int kc = (int)((t >> 5) & 15);
    long long F = t >> 9;

    uint4 o = make_uint4(0u, 0u, 0u, 0u);
    if (F * 16 + 15 < rows) {
        long long ra = F * 16 + (l >> 2);
        int ca = kc * 16 + (l & 3) * 2;
        float2 v00 = *(const float2*)(X + ra * D_IN + ca);
        float2 v10 = *(const float2*)(X + (ra + 8) * D_IN + ca);
        float2 v01 = *(const float2*)(X + ra * D_IN + ca + 8);
        float2 v11 = *(const float2*)(X + (ra + 8) * D_IN + ca + 8);
        o.x = packh2(v00.x, v00.y);
        o.y = packh2(v10.x, v10.y);
        o.z = packh2(v01.x, v01.y);
        o.w = packh2(v11.x, v11.y);
    }
    dst[t] = o;
}

// ---------------------------------------------------------------------------
// Prep W: frag-permuted fp16 B (m16n8k16); movie-root pair & biases combined.
// ---------------------------------------------------------------------------
__global__ void prep_w_kernel(
    const float* __restrict__ Wroot_dm, const float* __restrict__ Wroot_am,
    const float* __restrict__ Wroot_md, const float* __restrict__ Wroot_ma,
    const float* __restrict__ Wrel_dm,  const float* __restrict__ Wrel_am,
    const float* __restrict__ Wrel_md,  const float* __restrict__ Wrel_ma,
    const float* __restrict__ b_dm, const float* __restrict__ b_am,
    const float* __restrict__ b_md, const float* __restrict__ b_ma)
{
    int t = blockIdx.x * blockDim.x + threadIdx.x;
    if (t < 384) {
        if (t < 128)      g_bias[t] = b_dm[t] + b_am[t];
        else if (t < 256) g_bias[t] = b_md[t - 128];
        else              g_bias[t] = b_ma[t - 256];
    }
    if (t >= 7 * 4096) return;
    int widx = t >> 12;
    int r    = t & 4095;
    int kc   = r >> 8;
    int p    = (r >> 5) & 7;
    int l    = r & 31;

    const float* s1 = nullptr; const float* s2 = nullptr;
    switch (widx) {
        case 0: s1 = Wroot_dm; s2 = Wroot_am; break;
        case 1: s1 = Wroot_md; break;
        case 2: s1 = Wroot_ma; break;
        case 3: s1 = Wrel_dm; break;
        case 4: s1 = Wrel_am; break;
        case 5: s1 = Wrel_md; break;
        case 6: s1 = Wrel_ma; break;
    }
    int k0 = kc * 16 + (l & 3) * 2;
    uint32_t b[4];
    #pragma unroll
    for (int h = 0; h < 2; h++) {
        int n = (2 * p + h) * 8 + (l >> 2);
        float e0 = s1[(size_t)k0 * D_OUT + n];
        float e1 = s1[(size_t)(k0 + 1) * D_OUT + n];
        float e2 = s1[(size_t)(k0 + 8) * D_OUT + n];
        float e3 = s1[(size_t)(k0 + 9) * D_OUT + n];
        if (s2) {
            e0 += s2[(size_t)k0 * D_OUT + n];
            e1 += s2[(size_t)(k0 + 1) * D_OUT + n];
            e2 += s2[(size_t)(k0 + 8) * D_OUT + n];
            e3 += s2[(size_t)(k0 + 9) * D_OUT + n];
        }
        b[2 * h]     = packh2(e0, e1);
        b[2 * h + 1] = packh2(e2, e3);
    }
    g_wt[widx][(kc * 8 + p) * 32 + l] = make_uint4(b[0], b[1], b[2], b[3]);
}

// ---------------------------------------------------------------------------
// Fused multi-segment fp16 tensor-core GEMM. Up to 4 segments per launch,
// flat tile queue; B (64KB) reloaded only on segment crossings.
// 256 thr / 8 warps, warp tile M=32 x N=64, CTA tile M=128, 2 CTAs/SM.
// ---------------------------------------------------------------------------
struct GemmSeg {
    const uint4* A; const uint4* B; const float* bias; float* C;
    int M; int tileStart;
};
struct GemmSegs4 { GemmSeg s[4]; };

__global__ void __launch_bounds__(256, 2) fused_gemm_kernel(
    GemmSegs4 segs, int nseg, int totalTiles)
{
    extern __shared__ char smc[];          // B 65536 | bias 512 | A 2x16384
    uint4* Bs = (uint4*)smc;
    float* biasS = (float*)(smc + 65536);
    uint4* As = (uint4*)(smc + 66048);
    const uint32_t as_base = smem_u32(As);
    const int tid = threadIdx.x;
    const int wid = tid >> 5;
    const int l   = tid & 31;
    const int mq  = wid >> 1;
    const int nh  = wid & 1;
    int cur = -1;

    for (int t = blockIdx.x; t < totalTiles; t += gridDim.x) {
        int si = 0;
        #pragma unroll
        for (int k = 1; k < 4; k++)
            if (k < nseg && t >= segs.s[k].tileStart) si = k;
        const uint4* Afrag = segs.s[si].A;
        float* C = segs.s[si].C;
        const int M = segs.s[si].M;
        const int tile = t - segs.s[si].tileStart;

        __syncthreads();                   // prior tile's smem fully consumed
        if (si != cur) {                   // segment switch: reload B + bias
            const uint4* Bp = segs.s[si].B;
            #pragma unroll
            for (int i = 0; i < 16; i++) Bs[i * 256 + tid] = Bp[i * 256 + tid];
            const float* bp = segs.s[si].bias;
            if (tid < 128) biasS[tid] = bp ? bp[tid] : 0.f;
            cur = si;
        }

        const size_t Fbase = (size_t)tile * 8;
        auto stage = [&](int c, int b) {
            #pragma unroll
            for (int j = 0; j < 4; j++) {
                int i = j * 256 + tid;
                int ll = i & 31, kcL = (i >> 5) & 3, f = i >> 7;
                const uint4* src = Afrag + (Fbase + f) * 512 + (size_t)(c * 4 + kcL) * 32 + ll;
                uint32_t dst = as_base + (uint32_t)(b * 1024 + i) * 16;
                asm volatile("cp.async.ca.shared.global [%0], [%1], 16;"
                             :: "r"(dst), "l"(src));
            }
            asm volatile("cp.async.commit_group;");
        };

        stage(0, 0);
        stage(1, 1);

        float acc[2][8][4];
        #pragma unroll
        for (int fi = 0; fi < 2; fi++)
            #pragma unroll
            for (int j = 0; j < 8; j++)
                #pragma unroll
                for (int q = 0; q < 4; q++) acc[fi][j][q] = 0.f;

        #pragma unroll 1
        for (int c = 0; c < 4; c++) {
            if (c < 3) asm volatile("cp.async.wait_group 1;");
            else       asm volatile("cp.async.wait_group 0;");
            __syncthreads();               // A chunk ready (and B/bias visible)
            const int ab = (c & 1) * 1024;
            #pragma unroll
            for (int kcL = 0; kcL < 4; kcL++) {
                const int kc = c * 4 + kcL;
                uint4 a[2];
                #pragma unroll
                for (int fi = 0; fi < 2; fi++)
                    a[fi] = As[ab + ((mq * 2 + fi) * 4 + kcL) * 32 + l];
                #pragma unroll
                for (int p = 0; p < 4; p++) {
                    uint4 b4 = Bs[(kc * 8 + nh * 4 + p) * 32 + l];
                    #pragma unroll
                    for (int fi = 0; fi < 2; fi++) {
                        mma16(acc[fi][2 * p],     a[fi], b4.x, b4.y);
                        mma16(acc[fi][2 * p + 1], a[fi], b4.z, b4.w);
                    }
                }
            }
            if (c + 2 < 4) { __syncthreads(); stage(c + 2, c & 1); }
        }

        #pragma unroll
        for (int fi = 0; fi < 2; fi++) {
            long long r0 = (long long)tile * 128 + mq * 32 + fi * 16 + (l >> 2);
            #pragma unroll
            for (int j = 0; j < 8; j++) {
                int col = nh * 64 + j * 8 + 2 * (l & 3);
                float bx = biasS[col], by = biasS[col + 1];
                if (r0 < M) {
                    float2 v = make_float2(acc[fi][j][0] + bx, acc[fi][j][1] + by);
                    *(float2*)&C[r0 * D_OUT + col] = v;
                }
                if (r0 + 8 < M) {
                    float2 v = make_float2(acc[fi][j][2] + bx, acc[fi][j][3] + by);
                    *(float2*)&C[(r0 + 8) * D_OUT + col] = v;
                }
            }
        }
    }
}
#define SMEM_BYTES (66048 + 2 * 16384)   // 98816

// ---------------------------------------------------------------------------
// Gather by dst: warp per dst row; out[d] = relu(out[d] + sum y1[src] (+ y2)).
// ---------------------------------------------------------------------------
__global__ void gather_kernel(float* __restrict__ out, int n,
    const int* __restrict__ rp1, const int* __restrict__ es1, const float* __restrict__ y1,
    const int* __restrict__ rp2, const int* __restrict__ es2, const float* __restrict__ y2)
{
    int w = (int)(((long long)blockIdx.x * blockDim.x + threadIdx.x) >> 5);
    int lane = threadIdx.x & 31;
    if (w >= n) return;

    float4 acc = make_float4(0.f, 0.f, 0.f, 0.f);
    int b0 = __ldg(rp1 + w), b1 = __ldg(rp1 + w + 1);
    for (int e = b0; e < b1; e++) {
        int s = __ldg(es1 + e);
        float4 v = *(const float4*)(y1 + (size_t)s * D_OUT + lane * 4);
        acc.x += v.x; acc.y += v.y; acc.z += v.z; acc.w += v.w;
    }
    if (rp2) {
        int c0 = __ldg(rp2 + w), c1 = __ldg(rp2 + w + 1);
        for (int e = c0; e < c1; e++) {
            int s = __ldg(es2 + e);
            float4 v = *(const float4*)(y2 + (size_t)s * D_OUT + lane * 4);
            acc.x += v.x; acc.y += v.y; acc.z += v.z; acc.w += v.w;
        }
    }
    float* o = out + (size_t)w * D_OUT + lane * 4;
    float4 r = *(float4*)o;
    r.x = fmaxf(r.x + acc.x, 0.f);
    r.y = fmaxf(r.y + acc.y, 0.f);
    r.z = fmaxf(r.z + acc.z, 0.f);
    r.w = fmaxf(r.w + acc.w, 0.f);
    *(float4*)o = r;
}

// ---------------------------------------------------------------------------
extern "C" void kernel_launch(void* const* d_in, const int* in_sizes, int n_in,
                              void* d_out, int out_size)
{
    const float* x_movie = (const float*)d_in[0];
    const float* x_dir   = (const float*)d_in[1];
    const float* x_act   = (const float*)d_in[2];
    const int*   e_md    = (const int*)d_in[3];
    const int*   e_dm    = (const int*)d_in[4];
    const int*   e_ma    = (const int*)d_in[5];
    const int*   e_am    = (const int*)d_in[6];
    const float* W_rel_md  = (const float*)d_in[7];
    const float* b_md      = (const float*)d_in[8];
    const float* W_root_md = (const float*)d_in[9];
    const float* W_rel_dm  = (const float*)d_in[10];
    const float* b_dm      = (const float*)d_in[11];
    const float* W_root_dm = (const float*)d_in[12];
    const float* W_rel_ma  = (const float*)d_in[13];
    const float* b_ma      = (const float*)d_in[14];
    const float* W_root_ma = (const float*)d_in[15];
    const float* W_rel_am  = (const float*)d_in[16];
    const float* b_am      = (const float*)d_in[17];
    const float* W_root_am = (const float*)d_in[18];

    const int n_movie = in_sizes[0] / D_IN;
    const int n_dir   = in_sizes[1] / D_IN;
    const int n_act   = in_sizes[2] / D_IN;
    const int E_md = in_sizes[3] / 2;
    const int E_dm = in_sizes[4] / 2;
    const int E_ma = in_sizes[5] / 2;
    const int E_am = in_sizes[6] / 2;

    float* out_movie = (float*)d_out;
    float* out_dir   = out_movie + (size_t)n_movie * D_OUT;
    float* out_act   = out_dir + (size_t)n_dir * D_OUT;

    static float* scratch = nullptr;
    static uint4* xperm = nullptr;
    static uint4* wt = nullptr;
    static float* gbias = nullptr;
    static int *count = nullptr, *rowptr = nullptr, *cursor = nullptr,
               *chunks = nullptr, *esrc = nullptr;
    if (!scratch) cudaGetSymbolAddress((void**)&scratch, g_scratch);
    if (!xperm)   cudaGetSymbolAddress((void**)&xperm, g_xperm);
    if (!wt)      cudaGetSymbolAddress((void**)&wt, g_wt);
    if (!gbias)   cudaGetSymbolAddress((void**)&gbias, g_bias);
    if (!count)   cudaGetSymbolAddress((void**)&count, g_count);
    if (!rowptr)  cudaGetSymbolAddress((void**)&rowptr, g_rowptr);
    if (!cursor)  cudaGetSymbolAddress((void**)&cursor, g_cursor);
    if (!chunks)  cudaGetSymbolAddress((void**)&chunks, g_chunks);
    if (!esrc)    cudaGetSymbolAddress((void**)&esrc, g_esrc);

    float* sc_dm = scratch;
    float* sc_am = scratch + (size_t)50000 * 128;
    float* sc_md = scratch + (size_t)200000 * 128;
    float* sc_ma = scratch + (size_t)300000 * 128;

    cudaFuncSetAttribute(fused_gemm_kernel, cudaFuncAttributeMaxDynamicSharedMemorySize, SMEM_BYTES);

    cudaStream_t s0 = 0;
    cudaStream_t s2 = g_sp.s2;
    cudaStream_t s3 = g_sp.s3;

    const uint4* a_movie = xperm;
    const uint4* a_dir   = xperm + (size_t)FR_MOVIE * 512;
    const uint4* a_act   = xperm + (size_t)(FR_MOVIE + FR_DIR) * 512;

    auto build_csr = [&](int slot, const int* e32, int E, int ndst, cudaStream_t s) {
        int* cnt = count  + (size_t)slot * 150000;
        int* rp  = rowptr + (size_t)slot * 150001;
        int* cur = cursor + (size_t)slot * 150000;
        int* chk = chunks + (size_t)slot * 256;
        int* es  = esrc   + (size_t)slot * 320000;
        int nchunks = (ndst + 2047) / 2048;
        zero_i32<<<(ndst + 255) / 256, 256, 0, s>>>(cnt, ndst);
        hist_dst<<<(E + 255) / 256, 256, 0, s>>>(e32, E, cnt);
        scan_part<<<nchunks, 256, 0, s>>>(cnt, ndst, chk);
        scan_chunks<<<1, 256, 0, s>>>(chk, nchunks);
        scan_final<<<nchunks, 256, 0, s>>>(cnt, ndst, chk, rp, cur, E);
        fill_csr<<<(E + 255) / 256, 256, 0, s>>>(e32, E, cur, es);
    };
    auto prep_launch = [&](const float* X, uint4* dst, int nfrags, long long rows, cudaStream_t s) {
        long long tot = (long long)nfrags * 512;
        prep_a_one<<<(int)((tot + 255) / 256), 256, 0, s>>>(X, dst, nfrags, rows);
    };
    auto mkseg = [&](const uint4* A, int widx, const float* b, float* C, int M, int& tacc) {
        GemmSeg sg;
        sg.A = A; sg.B = wt + (size_t)widx * 4096; sg.bias = b; sg.C = C; sg.M = M;
        sg.tileStart = tacc;
        tacc += (M + 127) / 128;
        return sg;
    };

    // ---- head + fork ----
    detect_kernel<<<1, 32, 0, s0>>>(e_md);
    cudaEventRecord(g_sp.ev[8], s0);
    cudaStreamWaitEvent(s2, g_sp.ev[8], 0);
    cudaStreamWaitEvent(s3, g_sp.ev[8], 0);

    prep_w_kernel<<<(7 * 4096 + 255) / 256, 256, 0, s0>>>(
        W_root_dm, W_root_am, W_root_md, W_root_ma,
        W_rel_dm, W_rel_am, W_rel_md, W_rel_ma,
        b_dm, b_am, b_md, b_ma);
    prep_launch(x_act, (uint4*)a_act, FR_ACT + 8, n_act, s0);

    // s2: prep movie, then CSR ma (slot3) + md (slot2); later act/dir gathers.
    prep_launch(x_movie, (uint4*)a_movie, FR_MOVIE, n_movie, s2);
    cudaEventRecord(g_sp.ev[6], s2);
    build_csr(3, e_ma, E_ma, n_act, s2);
    build_csr(2, e_md, E_md, n_dir, s2);

    // s3: prep dir, then CSR dm (slot0) + am (slot1).
    prep_launch(x_dir, (uint4*)a_dir, FR_DIR, n_dir, s3);
    cudaEventRecord(g_sp.ev[7], s3);
    build_csr(0, e_dm, E_dm, n_movie, s3);
    build_csr(1, e_am, E_am, n_movie, s3);
    cudaEventRecord(g_sp.ev[2], s3);   // CSR dm+am ready

    // ---- fused GEMM launch 1: root act, rel ma, root movie ----
    cudaStreamWaitEvent(s0, g_sp.ev[6], 0);   // prep_movie done
    {
        GemmSegs4 segs{}; int tacc = 0;
        segs.s[0] = mkseg(a_act,   2, gbias + 256, out_act,   n_act,   tacc);
        segs.s[1] = mkseg(a_movie, 6, nullptr,     sc_ma,     n_movie, tacc);
        segs.s[2] = mkseg(a_movie, 0, gbias + 0,   out_movie, n_movie, tacc);
        int grid = tacc < 296 ? tacc : 296;
        fused_gemm_kernel<<<grid, 256, SMEM_BYTES, s0>>>(segs, 3, tacc);
    }
    cudaEventRecord(g_sp.ev[0], s0);          // root_act + y_ma + root_movie ready

    // ---- fused GEMM launch 2: rel am, rel md, root dir, rel dm ----
    cudaStreamWaitEvent(s0, g_sp.ev[7], 0);   // prep_dir done
    {
        GemmSegs4 segs{}; int tacc = 0;
        segs.s[0] = mkseg(a_act,   4, nullptr,     sc_am,   n_act,   tacc);
        segs.s[1] = mkseg(a_movie, 5, nullptr,     sc_md,   n_movie, tacc);
        segs.s[2] = mkseg(a_dir,   1, gbias + 128, out_dir, n_dir,   tacc);
        segs.s[3] = mkseg(a_dir,   3, nullptr,     sc_dm,   n_dir,   tacc);
        int grid = tacc < 296 ? tacc : 296;
        fused_gemm_kernel<<<grid, 256, SMEM_BYTES, s0>>>(segs, 4, tacc);
    }
    cudaEventRecord(g_sp.ev[1], s0);          // all remaining products ready

    // ---- gathers (relu fused) ----
    // act: relation ma — on s2 (CSR ma built there in-order); overlaps launch 2.
    cudaStreamWaitEvent(s2, g_sp.ev[0], 0);
    gather_kernel<<<((n_act * 32) + 255) / 256, 256, 0, s2>>>(
        out_act, n_act,
        rowptr + (size_t)3 * 150001, esrc + (size_t)3 * 320000, sc_ma,
        nullptr, nullptr, nullptr);
    // dir: relation md — on s2 after launch 2.
    cudaStreamWaitEvent(s2, g_sp.ev[1], 0);
    gather_kernel<<<((n_dir * 32) + 255) / 256, 256, 0, s2>>>(
        out_dir, n_dir,
        rowptr + (size_t)2 * 150001, esrc + (size_t)2 * 320000, sc_md,
        nullptr, nullptr, nullptr);
    cudaEventRecord(g_sp.ev[3], s2);

    // movie: relations dm + am — on s0 after launch 2 (in-order) + CSRs from s3.
    cudaStreamWaitEvent(s0, g_sp.ev[2], 0);
    gather_kernel<<<((n_movie * 32) + 255) / 256, 256, 0, s0>>>(
        out_movie, n_movie,
        rowptr + (size_t)0 * 150001, esrc + (size_t)0 * 320000, sc_dm,
        rowptr + (size_t)1 * 150001, esrc + (size_t)1 * 320000, sc_am);

    // join s2 back.
    cudaStreamWaitEvent(s0, g_sp.ev[3], 0);
}

// round 14
// speedup vs baseline: 1.0067x; 1.0067x over previous
#include <cuda_runtime.h>
#include <cuda_fp16.h>
#include <cstdint>

#define D_IN  256
#define D_OUT 128

// 16-row fragment counts: movie 6250, dir 3125, act 9375 (+8 pad)
#define FR_MOVIE 6250
#define FR_DIR   3125
#define FR_ACT   9375
#define FR_TOTAL 18758

__device__ uint4 g_xperm[(size_t)FR_TOTAL * 512];  // frag-permuted fp16 X
__device__ uint4 g_wt[7][4096];                    // frag-permuted fp16 W
__device__ float g_bias[384];
// y buffers: dm@0 (50k rows), am@50k (150k), md@200k (100k), ma@300k (100k).
__device__ float g_scratch[(size_t)400000 * 128];
__device__ int g_e_is64;

// CSR-by-dst per relation: slot 0=dm, 1=am, 2=md, 3=ma.
__device__ int g_count[4][150000];
__device__ int g_rowptr[4][150001];
__device__ int g_cursor[4][150000];
__device__ int g_chunks[4][256];
__device__ int g_esrc[4][320000];

struct StreamPack {
    cudaStream_t s2, s3;
    cudaEvent_t ev[10];
    StreamPack() {
        cudaStreamCreateWithFlags(&s2, cudaStreamNonBlocking);
        cudaStreamCreateWithFlags(&s3, cudaStreamNonBlocking);
        for (int i = 0; i < 10; i++) cudaEventCreateWithFlags(&ev[i], cudaEventDisableTiming);
    }
};
static StreamPack g_sp;

__device__ __forceinline__ uint32_t packh2(float x, float y) {
    __half2 h = __floats2half2_rn(x, y);
    return *(uint32_t*)&h;
}
__device__ __forceinline__ uint32_t smem_u32(const void* p) {
    uint32_t a;
    asm("{ .reg .u64 t; cvta.to.shared.u64 t, %1; cvt.u32.u64 %0, t; }" : "=r"(a) : "l"(p));
    return a;
}
__device__ __forceinline__ void mma16(float* d, uint4 a, uint32_t b0, uint32_t b1) {
    asm volatile("mma.sync.aligned.m16n8k16.row.col.f32.f16.f16.f32 "
        "{%0,%1,%2,%3}, {%4,%5,%6,%7}, {%8,%9}, {%0,%1,%2,%3};"
        : "+f"(d[0]), "+f"(d[1]), "+f"(d[2]), "+f"(d[3])
        : "r"(a.x), "r"(a.y), "r"(a.z), "r"(a.w), "r"(b0), "r"(b1));
}

// ---------------------------------------------------------------------------
__global__ void detect_kernel(const int* __restrict__ e32) {
    if (threadIdx.x == 0 && blockIdx.x == 0) {
        int all0 = 1;
        for (int i = 1; i < 64; i += 2) all0 &= (e32[i] == 0);
        g_e_is64 = all0;
    }
}

// ---------------------------------------------------------------------------
// CSR-by-dst build kernels
// ---------------------------------------------------------------------------
__global__ void zero_i32(int* __restrict__ p, int n) {
    int i = blockIdx.x * blockDim.x + threadIdx.x;
    if (i < n) p[i] = 0;
}
__global__ void hist_dst(const int* __restrict__ e32, int E, int* __restrict__ count) {
    int e = blockIdx.x * blockDim.x + threadIdx.x;
    if (e >= E) return;
    int mult = g_e_is64 ? 2 : 1;
    int d = e32[(size_t)(E + e) * mult];
    atomicAdd(&count[d], 1);
}
__global__ void scan_part(const int* __restrict__ cnt, int n, int* __restrict__ sums) {
    __shared__ int sm[256];
    int b = blockIdx.x, t = threadIdx.x;
    int base = b * 2048 + t * 8;
    int s = 0;
    #pragma unroll
    for (int i = 0; i < 8; i++) { int idx = base + i; if (idx < n) s += cnt[idx]; }
    sm[t] = s; __syncthreads();
    for (int o = 128; o > 0; o >>= 1) { if (t < o) sm[t] += sm[t + o]; __syncthreads(); }
    if (t == 0) sums[b] = sm[0];
}
__global__ void scan_chunks(int* __restrict__ sums, int nc) {
    __shared__ int sm[256];
    int t = threadIdx.x;
    int orig = (t < nc) ? sums[t] : 0;
    sm[t] = orig; __syncthreads();
    for (int o = 1; o < 256; o <<= 1) {
        int u = (t >= o) ? sm[t - o] : 0;
        __syncthreads();
        sm[t] += u;
        __syncthreads();
    }
    if (t < nc) sums[t] = sm[t] - orig;   // exclusive
}
__global__ void scan_final(const int* __restrict__ cnt, int n,
                           const int* __restrict__ chunkOff,
                           int* __restrict__ rowptr, int* __restrict__ cursor, int E) {
    __shared__ int sm[256];
    int b = blockIdx.x, t = threadIdx.x;
    int base = b * 2048 + t * 8;
    int v[8]; int s = 0;
    #pragma unroll
    for (int i = 0; i < 8; i++) { int idx = base + i; v[i] = (idx < n) ? cnt[idx] : 0; s += v[i]; }
    int orig = s;
    sm[t] = s; __syncthreads();
    for (int o = 1; o < 256; o <<= 1) {
        int u = (t >= o) ? sm[t - o] : 0;
        __syncthreads();
        sm[t] += u;
        __syncthreads();
    }
    int run = chunkOff[b] + (sm[t] - orig);
    #pragma unroll
    for (int i = 0; i < 8; i++) {
        int idx = base + i;
        if (idx < n) { rowptr[idx] = run; cursor[idx] = run; run += v[i]; }
    }
    if (b == 0 && t == 0) rowptr[n] = E;
}
__global__ void fill_csr(const int* __restrict__ e32, int E,
                         int* __restrict__ cursor, int* __restrict__ esrc) {
    int e = blockIdx.x * blockDim.x + threadIdx.x;
    if (e >= E) return;
    int mult = g_e_is64 ? 2 : 1;
    int s = e32[(size_t)e * mult];
    int d = e32[(size_t)(E + e) * mult];
    int pos = atomicAdd(&cursor[d], 1);
    esrc[pos] = s;
}

// ---------------------------------------------------------------------------
// Prep A (one matrix): permute into m16n8k16 fp16 A-fragment order.
// ---------------------------------------------------------------------------
__global__ void prep_a_one(const float* __restrict__ X, uint4* __restrict__ dst,
                           int nfrags, long long rows)
{
    long long t = (long long)blockIdx.x * blockDim.x + threadIdx.x;
    if (t >= (long long)nfrags * 512) return;
    int l  = (int)(t & 31);
    int kc = (int)((t >> 5) & 15);
    long long F = t >> 9;

    uint4 o = make_uint4(0u, 0u, 0u, 0u);
    if (F * 16 + 15 < rows) {
        long long ra = F * 16 + (l >> 2);
        int ca = kc * 16 + (l & 3) * 2;
        float2 v00 = *(const float2*)(X + ra * D_IN + ca);
        float2 v10 = *(const float2*)(X + (ra + 8) * D_IN + ca);
        float2 v01 = *(const float2*)(X + ra * D_IN + ca + 8);
        float2 v11 = *(const float2*)(X + (ra + 8) * D_IN + ca + 8);
        o.x = packh2(v00.x, v00.y);
        o.y = packh2(v10.x, v10.y);
        o.z = packh2(v01.x, v01.y);
        o.w = packh2(v11.x, v11.y);
    }
    dst[t] = o;
}

// ---------------------------------------------------------------------------
// Prep W: frag-permuted fp16 B (m16n8k16); movie-root pair & biases combined.
// ---------------------------------------------------------------------------
__global__ void prep_w_kernel(
    const float* __restrict__ Wroot_dm, const float* __restrict__ Wroot_am,
    const float* __restrict__ Wroot_md, const float* __restrict__ Wroot_ma,
    const float* __restrict__ Wrel_dm,  const float* __restrict__ Wrel_am,
    const float* __restrict__ Wrel_md,  const float* __restrict__ Wrel_ma,
    const float* __restrict__ b_dm, const float* __restrict__ b_am,
    const float* __restrict__ b_md, const float* __restrict__ b_ma)
{
    int t = blockIdx.x * blockDim.x + threadIdx.x;
    if (t < 384) {
        if (t < 128)      g_bias[t] = b_dm[t] + b_am[t];
        else if (t < 256) g_bias[t] = b_md[t - 128];
        else              g_bias[t] = b_ma[t - 256];
    }
    if (t >= 7 * 4096) return;
    int widx = t >> 12;
    int r    = t & 4095;
    int kc   = r >> 8;
    int p    = (r >> 5) & 7;
    int l    = r & 31;

    const float* s1 = nullptr; const float* s2 = nullptr;
    switch (widx) {
        case 0: s1 = Wroot_dm; s2 = Wroot_am; break;
        case 1: s1 = Wroot_md; break;
        case 2: s1 = Wroot_ma; break;
        case 3: s1 = Wrel_dm; break;
        case 4: s1 = Wrel_am; break;
        case 5: s1 = Wrel_md; break;
        case 6: s1 = Wrel_ma; break;
    }
    int k0 = kc * 16 + (l & 3) * 2;
    uint32_t b[4];
    #pragma unroll
    for (int h = 0; h < 2; h++) {
        int n = (2 * p + h) * 8 + (l >> 2);
        float e0 = s1[(size_t)k0 * D_OUT + n];
        float e1 = s1[(size_t)(k0 + 1) * D_OUT + n];
        float e2 = s1[(size_t)(k0 + 8) * D_OUT + n];
        float e3 = s1[(size_t)(k0 + 9) * D_OUT + n];
        if (s2) {
            e0 += s2[(size_t)k0 * D_OUT + n];
            e1 += s2[(size_t)(k0 + 1) * D_OUT + n];
            e2 += s2[(size_t)(k0 + 8) * D_OUT + n];
            e3 += s2[(size_t)(k0 + 9) * D_OUT + n];
        }
        b[2 * h]     = packh2(e0, e1);
        b[2 * h + 1] = packh2(e2, e3);
    }
    g_wt[widx][(kc * 8 + p) * 32 + l] = make_uint4(b[0], b[1], b[2], b[3]);
}

// ---------------------------------------------------------------------------
// Fused multi-segment fp16 tensor-core GEMM. Up to 4 segments per launch,
// flat tile queue; B (64KB) reloaded only on segment crossings.
// 256 thr / 8 warps, warp tile M=32 x N=64, CTA tile M=128, 2 CTAs/SM.
// ---------------------------------------------------------------------------
struct GemmSeg {
    const uint4* A; const uint4* B; const float* bias; float* C;
    int M; int tileStart;
};
struct GemmSegs4 { GemmSeg s[4]; };

__global__ void __launch_bounds__(256, 2) fused_gemm_kernel(
    GemmSegs4 segs, int nseg, int totalTiles)
{
    extern __shared__ char smc[];          // B 65536 | bias 512 | A 2x16384
    uint4* Bs = (uint4*)smc;
    float* biasS = (float*)(smc + 65536);
    uint4* As = (uint4*)(smc + 66048);
    const uint32_t as_base = smem_u32(As);
    const int tid = threadIdx.x;
    const int wid = tid >> 5;
    const int l   = tid & 31;
    const int mq  = wid >> 1;
    const int nh  = wid & 1;
    int cur = -1;

    for (int t = blockIdx.x; t < totalTiles; t += gridDim.x) {
        int si = 0;
        #pragma unroll
        for (int k = 1; k < 4; k++)
            if (k < nseg && t >= segs.s[k].tileStart) si = k;
        const uint4* Afrag = segs.s[si].A;
        float* C = segs.s[si].C;
        const int M = segs.s[si].M;
        const int tile = t - segs.s[si].tileStart;

        __syncthreads();                   // prior tile's smem fully consumed
        if (si != cur) {                   // segment switch: reload B + bias
            const uint4* Bp = segs.s[si].B;
            #pragma unroll
            for (int i = 0; i < 16; i++) Bs[i * 256 + tid] = Bp[i * 256 + tid];
            const float* bp = segs.s[si].bias;
            if (tid < 128) biasS[tid] = bp ? bp[tid] : 0.f;
            cur = si;
        }

        const size_t Fbase = (size_t)tile * 8;
        auto stage = [&](int c, int b) {
            #pragma unroll
            for (int j = 0; j < 4; j++) {
                int i = j * 256 + tid;
                int ll = i & 31, kcL = (i >> 5) & 3, f = i >> 7;
                const uint4* src = Afrag + (Fbase + f) * 512 + (size_t)(c * 4 + kcL) * 32 + ll;
                uint32_t dst = as_base + (uint32_t)(b * 1024 + i) * 16;
                asm volatile("cp.async.ca.shared.global [%0], [%1], 16;"
                             :: "r"(dst), "l"(src));
            }
            asm volatile("cp.async.commit_group;");
        };

        stage(0, 0);
        stage(1, 1);

        float acc[2][8][4];
        #pragma unroll
        for (int fi = 0; fi < 2; fi++)
            #pragma unroll
            for (int j = 0; j < 8; j++)
                #pragma unroll
                for (int q = 0; q < 4; q++) acc[fi][j][q] = 0.f;

        #pragma unroll 1
        for (int c = 0; c < 4; c++) {
            if (c < 3) asm volatile("cp.async.wait_group 1;");
            else       asm volatile("cp.async.wait_group 0;");
            __syncthreads();               // A chunk ready (and B/bias visible)
            const int ab = (c & 1) * 1024;
            #pragma unroll
            for (int kcL = 0; kcL < 4; kcL++) {
                const int kc = c * 4 + kcL;
                uint4 a[2];
                #pragma unroll
                for (int fi = 0; fi < 2; fi++)
                    a[fi] = As[ab + ((mq * 2 + fi) * 4 + kcL) * 32 + l];
                #pragma unroll
                for (int p = 0; p < 4; p++) {
                    uint4 b4 = Bs[(kc * 8 + nh * 4 + p) * 32 + l];
                    #pragma unroll
                    for (int fi = 0; fi < 2; fi++) {
                        mma16(acc[fi][2 * p],     a[fi], b4.x, b4.y);
                        mma16(acc[fi][2 * p + 1], a[fi], b4.z, b4.w);
                    }
                }
            }
            if (c + 2 < 4) { __syncthreads(); stage(c + 2, c & 1); }
        }

        #pragma unroll
        for (int fi = 0; fi < 2; fi++) {
            long long r0 = (long long)tile * 128 + mq * 32 + fi * 16 + (l >> 2);
            #pragma unroll
            for (int j = 0; j < 8; j++) {
                int col = nh * 64 + j * 8 + 2 * (l & 3);
                float bx = biasS[col], by = biasS[col + 1];
                if (r0 < M) {
                    float2 v = make_float2(acc[fi][j][0] + bx, acc[fi][j][1] + by);
                    *(float2*)&C[r0 * D_OUT + col] = v;
                }
                if (r0 + 8 < M) {
                    float2 v = make_float2(acc[fi][j][2] + bx, acc[fi][j][3] + by);
                    *(float2*)&C[(r0 + 8) * D_OUT + col] = v;
                }
            }
        }
    }
}
#define SMEM_BYTES (66048 + 2 * 16384)   // 98816

// ---------------------------------------------------------------------------
// Gather by dst: warp per dst row; out[d] = relu(out[d] + sum y1[src] (+ y2)).
// ---------------------------------------------------------------------------
__global__ void gather_kernel(float* __restrict__ out, int n,
    const int* __restrict__ rp1, const int* __restrict__ es1, const float* __restrict__ y1,
    const int* __restrict__ rp2, const int* __restrict__ es2, const float* __restrict__ y2)
{
    int w = (int)(((long long)blockIdx.x * blockDim.x + threadIdx.x) >> 5);
    int lane = threadIdx.x & 31;
    if (w >= n) return;

    float4 acc = make_float4(0.f, 0.f, 0.f, 0.f);
    int b0 = __ldg(rp1 + w), b1 = __ldg(rp1 + w + 1);
    for (int e = b0; e < b1; e++) {
        int s = __ldg(es1 + e);
        float4 v = *(const float4*)(y1 + (size_t)s * D_OUT + lane * 4);
        acc.x += v.x; acc.y += v.y; acc.z += v.z; acc.w += v.w;
    }
    if (rp2) {
        int c0 = __ldg(rp2 + w), c1 = __ldg(rp2 + w + 1);
        for (int e = c0; e < c1; e++) {
            int s = __ldg(es2 + e);
            float4 v = *(const float4*)(y2 + (size_t)s * D_OUT + lane * 4);
            acc.x += v.x; acc.y += v.y; acc.z += v.z; acc.w += v.w;
        }
    }
    float* o = out + (size_t)w * D_OUT + lane * 4;
    float4 r = *(float4*)o;
    r.x = fmaxf(r.x + acc.x, 0.f);
    r.y = fmaxf(r.y + acc.y, 0.f);
    r.z = fmaxf(r.z + acc.z, 0.f);
    r.w = fmaxf(r.w + acc.w, 0.f);
    *(float4*)o = r;
}

// ---------------------------------------------------------------------------
extern "C" void kernel_launch(void* const* d_in, const int* in_sizes, int n_in,
                              void* d_out, int out_size)
{
    const float* x_movie = (const float*)d_in[0];
    const float* x_dir   = (const float*)d_in[1];
    const float* x_act   = (const float*)d_in[2];
    const int*   e_md    = (const int*)d_in[3];
    const int*   e_dm    = (const int*)d_in[4];
    const int*   e_ma    = (const int*)d_in[5];
    const int*   e_am    = (const int*)d_in[6];
    const float* W_rel_md  = (const float*)d_in[7];
    const float* b_md      = (const float*)d_in[8];
    const float* W_root_md = (const float*)d_in[9];
    const float* W_rel_dm  = (const float*)d_in[10];
    const float* b_dm      = (const float*)d_in[11];
    const float* W_root_dm = (const float*)d_in[12];
    const float* W_rel_ma  = (const float*)d_in[13];
    const float* b_ma      = (const float*)d_in[14];
    const float* W_root_ma = (const float*)d_in[15];
    const float* W_rel_am  = (const float*)d_in[16];
    const float* b_am      = (const float*)d_in[17];
    const float* W_root_am = (const float*)d_in[18];

    const int n_movie = in_sizes[0] / D_IN;
    const int n_dir   = in_sizes[1] / D_IN;
    const int n_act   = in_sizes[2] / D_IN;
    const int E_md = in_sizes[3] / 2;
    const int E_dm = in_sizes[4] / 2;
    const int E_ma = in_sizes[5] / 2;
    const int E_am = in_sizes[6] / 2;

    float* out_movie = (float*)d_out;
    float* out_dir   = out_movie + (size_t)n_movie * D_OUT;
    float* out_act   = out_dir + (size_t)n_dir * D_OUT;

    static float* scratch = nullptr;
    static uint4* xperm = nullptr;
    static uint4* wt = nullptr;
    static float* gbias = nullptr;
    static int *count = nullptr, *rowptr = nullptr, *cursor = nullptr,
               *chunks = nullptr, *esrc = nullptr;
    if (!scratch) cudaGetSymbolAddress((void**)&scratch, g_scratch);
    if (!xperm)   cudaGetSymbolAddress((void**)&xperm, g_xperm);
    if (!wt)      cudaGetSymbolAddress((void**)&wt, g_wt);
    if (!gbias)   cudaGetSymbolAddress((void**)&gbias, g_bias);
    if (!count)   cudaGetSymbolAddress((void**)&count, g_count);
    if (!rowptr)  cudaGetSymbolAddress((void**)&rowptr, g_rowptr);
    if (!cursor)  cudaGetSymbolAddress((void**)&cursor, g_cursor);
    if (!chunks)  cudaGetSymbolAddress((void**)&chunks, g_chunks);
    if (!esrc)    cudaGetSymbolAddress((void**)&esrc, g_esrc);

    float* sc_dm = scratch;
    float* sc_am = scratch + (size_t)50000 * 128;
    float* sc_md = scratch + (size_t)200000 * 128;
    float* sc_ma = scratch + (size_t)300000 * 128;

    cudaFuncSetAttribute(fused_gemm_kernel, cudaFuncAttributeMaxDynamicSharedMemorySize, SMEM_BYTES);

    cudaStream_t s0 = 0;
    cudaStream_t s2 = g_sp.s2;
    cudaStream_t s3 = g_sp.s3;

    const uint4* a_movie = xperm;
    const uint4* a_dir   = xperm + (size_t)FR_MOVIE * 512;
    const uint4* a_act   = xperm + (size_t)(FR_MOVIE + FR_DIR) * 512;

    auto build_csr = [&](int slot, const int* e32, int E, int ndst, cudaStream_t s) {
        int* cnt = count  + (size_t)slot * 150000;
        int* rp  = rowptr + (size_t)slot * 150001;
        int* cur = cursor + (size_t)slot * 150000;
        int* chk = chunks + (size_t)slot * 256;
        int* es  = esrc   + (size_t)slot * 320000;
        int nchunks = (ndst + 2047) / 2048;
        zero_i32<<<(ndst + 255) / 256, 256, 0, s>>>(cnt, ndst);
        hist_dst<<<(E + 255) / 256, 256, 0, s>>>(e32, E, cnt);
        scan_part<<<nchunks, 256, 0, s>>>(cnt, ndst, chk);
        scan_chunks<<<1, 256, 0, s>>>(chk, nchunks);
        scan_final<<<nchunks, 256, 0, s>>>(cnt, ndst, chk, rp, cur, E);
        fill_csr<<<(E + 255) / 256, 256, 0, s>>>(e32, E, cur, es);
    };
    auto prep_launch = [&](const float* X, uint4* dst, int nfrags, long long rows, cudaStream_t s) {
        long long tot = (long long)nfrags * 512;
        prep_a_one<<<(int)((tot + 255) / 256), 256, 0, s>>>(X, dst, nfrags, rows);
    };
    auto mkseg = [&](const uint4* A, int widx, const float* b, float* C, int M, int& tacc) {
        GemmSeg sg;
        sg.A = A; sg.B = wt + (size_t)widx * 4096; sg.bias = b; sg.C = C; sg.M = M;
        sg.tileStart = tacc;
        tacc += (M + 127) / 128;
        return sg;
    };

    // ---- head + fork ----
    detect_kernel<<<1, 32, 0, s0>>>(e_md);
    cudaEventRecord(g_sp.ev[8], s0);
    cudaStreamWaitEvent(s2, g_sp.ev[8], 0);
    cudaStreamWaitEvent(s3, g_sp.ev[8], 0);

    prep_w_kernel<<<(7 * 4096 + 255) / 256, 256, 0, s0>>>(
        W_root_dm, W_root_am, W_root_md, W_root_ma,
        W_rel_dm, W_rel_am, W_rel_md, W_rel_ma,
        b_dm, b_am, b_md, b_ma);
    prep_launch(x_act, (uint4*)a_act, FR_ACT + 8, n_act, s0);

    // s2: prep movie, then CSR ma (slot3) + md (slot2); later act/dir gathers.
    prep_launch(x_movie, (uint4*)a_movie, FR_MOVIE, n_movie, s2);
    cudaEventRecord(g_sp.ev[6], s2);
    build_csr(3, e_ma, E_ma, n_act, s2);
    build_csr(2, e_md, E_md, n_dir, s2);

    // s3: prep dir, then CSR dm (slot0) + am (slot1).
    prep_launch(x_dir, (uint4*)a_dir, FR_DIR, n_dir, s3);
    cudaEventRecord(g_sp.ev[7], s3);
    build_csr(0, e_dm, E_dm, n_movie, s3);
    build_csr(1, e_am, E_am, n_movie, s3);
    cudaEventRecord(g_sp.ev[2], s3);   // CSR dm+am ready

    // ---- fused GEMM launch 1: root act, rel ma, root movie ----
    cudaStreamWaitEvent(s0, g_sp.ev[6], 0);   // prep_movie done
    {
        GemmSegs4 segs{}; int tacc = 0;
        segs.s[0] = mkseg(a_act,   2, gbias + 256, out_act,   n_act,   tacc);
        segs.s[1] = mkseg(a_movie, 6, nullptr,     sc_ma,     n_movie, tacc);
        segs.s[2] = mkseg(a_movie, 0, gbias + 0,   out_movie, n_movie, tacc);
        int grid = tacc < 296 ? tacc : 296;
        fused_gemm_kernel<<<grid, 256, SMEM_BYTES, s0>>>(segs, 3, tacc);
    }
    cudaEventRecord(g_sp.ev[0], s0);          // root_act + y_ma + root_movie ready

    // ---- fused GEMM launch 2: rel am, rel md, root dir, rel dm ----
    cudaStreamWaitEvent(s0, g_sp.ev[7], 0);   // prep_dir done
    {
        GemmSegs4 segs{}; int tacc = 0;
        segs.s[0] = mkseg(a_act,   4, nullptr,     sc_am,   n_act,   tacc);
        segs.s[1] = mkseg(a_movie, 5, nullptr,     sc_md,   n_movie, tacc);
        segs.s[2] = mkseg(a_dir,   1, gbias + 128, out_dir, n_dir,   tacc);
        segs.s[3] = mkseg(a_dir,   3, nullptr,     sc_dm,   n_dir,   tacc);
        int grid = tacc < 296 ? tacc : 296;
        fused_gemm_kernel<<<grid, 256, SMEM_BYTES, s0>>>(segs, 4, tacc);
    }
    cudaEventRecord(g_sp.ev[1], s0);          // all remaining products ready

    // ---- gathers (relu fused) ----
    // act: relation ma — on s2 (CSR ma built there in-order); overlaps launch 2.
    cudaStreamWaitEvent(s2, g_sp.ev[0], 0);
    gather_kernel<<<((n_act * 32) + 255) / 256, 256, 0, s2>>>(
        out_act, n_act,
        rowptr + (size_t)3 * 150001, esrc + (size_t)3 * 320000, sc_ma,
        nullptr, nullptr, nullptr);
    // dir: relation md — on s2 after launch 2.
    cudaStreamWaitEvent(s2, g_sp.ev[1], 0);
    gather_kernel<<<((n_dir * 32) + 255) / 256, 256, 0, s2>>>(
        out_dir, n_dir,
        rowptr + (size_t)2 * 150001, esrc + (size_t)2 * 320000, sc_md,
        nullptr, nullptr, nullptr);
    cudaEventRecord(g_sp.ev[3], s2);

    // movie: relations dm + am — on s0 after launch 2 (in-order) + CSRs from s3.
    cudaStreamWaitEvent(s0, g_sp.ev[2], 0);
    gather_kernel<<<((n_movie * 32) + 255) / 256, 256, 0, s0>>>(
        out_movie, n_movie,
        rowptr + (size_t)0 * 150001, esrc + (size_t)0 * 320000, sc_dm,
        rowptr + (size_t)1 * 150001, esrc + (size_t)1 * 320000, sc_am);

    // join s2 back.
    cudaStreamWaitEvent(s0, g_sp.ev[3], 0);
}